// round 16
// baseline (speedup 1.0000x reference)
#include <cuda_runtime.h>
#include <math.h>

#define NB 8
#define NN 4096
#define KK 30
#define FULLMASK 0xFFFFFFFFu

// Packed-pair fp32 helpers (sm_103a: FFMA2 only reachable via PTX f32x2)
#define FMA_F32X2(d, a, b) \
    asm("fma.rn.f32x2 %0, %1, %2, %0;" : "+l"(d) : "l"(a), "l"(b))
#define PACK2(d, lo, hi) \
    asm("mov.b64 %0, {%1, %2};" : "=l"(d) : "f"(lo), "f"(hi))
#define UNPACK2(lo, hi, d) \
    asm("mov.b64 {%0, %1}, %2;" : "=f"(lo), "=f"(hi) : "l"(d))

// scratch: knn indices (sorted by (pd desc, idx asc)), 8*4096*30 ints = 3.93 MB
__device__ int g_knn[NB * NN * KK];

// ---------------------------------------------------------------------------
// Kernel 1: exact top-30 KNN — identical to the R11-measured kernel.
// ---------------------------------------------------------------------------
__global__ __launch_bounds__(256) void knn_kernel(const float* __restrict__ x) {
    extern __shared__ float4 sm4[];      // NN float4 = 64 KB

    int b     = blockIdx.x >> 9;            // 512 blocks per batch element
    int nbase = (blockIdx.x & 511) * 8;     // 8 rows (warps) per block
    const float* xb = x + (size_t)b * 3 * NN;

    for (int i = threadIdx.x; i < NN; i += 256) {
        float a0 = xb[i], a1 = xb[NN + i], a2 = xb[2 * NN + i];
        float xx = __fadd_rn(__fadd_rn(__fmul_rn(a0, a0), __fmul_rn(a1, a1)),
                             __fmul_rn(a2, a2));
        sm4[i] = make_float4(a0, a1, a2, xx);
    }
    __syncthreads();

    int warp = threadIdx.x >> 5;
    int lane = threadIdx.x & 31;
    int n = nbase + warp;

    float4 q = sm4[n];
    float cx = q.x, cy = q.y, cz = q.z, xxn = q.w;

    unsigned long long v = 0ULL;   // sentinel (all real keys are > 0)
    float thr = -INFINITY;         // pd of rank-29 entry (-inf while filling)

    #pragma unroll 1
    for (int t = 0; t < NN / 128; ++t) {
        int m0 = t * 128 + lane;
        float4 c0 = sm4[m0];
        float4 c1 = sm4[m0 + 32];
        float4 c2 = sm4[m0 + 64];
        float4 c3 = sm4[m0 + 96];
        float i0 = __fadd_rn(__fadd_rn(__fmul_rn(cx, c0.x), __fmul_rn(cy, c0.y)), __fmul_rn(cz, c0.z));
        float i1 = __fadd_rn(__fadd_rn(__fmul_rn(cx, c1.x), __fmul_rn(cy, c1.y)), __fmul_rn(cz, c1.z));
        float i2 = __fadd_rn(__fadd_rn(__fmul_rn(cx, c2.x), __fmul_rn(cy, c2.y)), __fmul_rn(cz, c2.z));
        float i3 = __fadd_rn(__fadd_rn(__fmul_rn(cx, c3.x), __fmul_rn(cy, c3.y)), __fmul_rn(cz, c3.z));
        float pd0 = __fsub_rn(__fsub_rn(__fmul_rn(2.0f, i0), c0.w), xxn);
        float pd1 = __fsub_rn(__fsub_rn(__fmul_rn(2.0f, i1), c1.w), xxn);
        float pd2 = __fsub_rn(__fsub_rn(__fmul_rn(2.0f, i2), c2.w), xxn);
        float pd3 = __fsub_rn(__fsub_rn(__fmul_rn(2.0f, i3), c3.w), xxn);

        bool hit = (pd0 > thr) | (pd1 > thr) | (pd2 > thr) | (pd3 > thr);
        if (__ballot_sync(FULLMASK, hit)) {      // warp-uniform rare path
            #pragma unroll
            for (int s = 0; s < 4; ++s) {
                float pd = (s == 0) ? pd0 : (s == 1) ? pd1 : (s == 2) ? pd2 : pd3;
                int   m  = m0 + s * 32;
                unsigned insmask = __ballot_sync(FULLMASK, pd > thr);
                if (insmask) {
                    unsigned ou = __float_as_uint(pd);
                    ou = (ou & 0x80000000u) ? ~ou : (ou | 0x80000000u);
                    unsigned long long key =
                        ((unsigned long long)ou << 32) |
                        (unsigned long long)(0xFFFFFFFFu - (unsigned)m);

                    unsigned long long thrk = __shfl_sync(FULLMASK, v, 29);
                    while (insmask) {
                        int sl = __ffs(insmask) - 1;
                        insmask &= insmask - 1;
                        unsigned long long K = __shfl_sync(FULLMASK, key, sl);
                        if (K > thrk) {          // warp-uniform
                            unsigned gt = __ballot_sync(FULLMASK, v > K) & 0x3FFFFFFFu;
                            int pos = __popc(gt);
                            unsigned long long up = __shfl_up_sync(FULLMASK, v, 1);
                            if (lane < 30 && lane >= pos) v = (lane == pos) ? K : up;
                            thrk = __shfl_sync(FULLMASK, v, 29);
                        }
                    }
                    unsigned hi = (unsigned)(thrk >> 32);
                    if (hi) {    // hi==0 <=> list not yet full -> keep -inf
                        unsigned ob = (hi & 0x80000000u) ? (hi & 0x7FFFFFFFu) : ~hi;
                        thr = __uint_as_float(ob);
                    }
                }
            }
        }
    }

    if (lane < 30) {
        g_knn[((size_t)b * NN + n) * KK + lane] =
            (int)(0xFFFFFFFFu - (unsigned)(v & 0xFFFFFFFFull));
    }
}

// ---------------------------------------------------------------------------
// Kernel 2 (GEMM-structured): block = 256 thr = 8 warps handles 4 points.
// Phase A: 128 threads build h1[64][128] (col = point*32+j) in smem.
// Phase B: register-tiled GEMM  h2 = lrelu(w2t^T @ h1 + b2):
//   warp = (rowgrp 0..3, colgrp 0..1); thread = 4 rows x 8 cols C-tile
//   (32 u64 f32x2 accums). Per k: 1 A-LDS.128 + 2 B-LDS.128 -> 16 FFMA2.
// Phase C: attention logit (split over 2 warps/point) + prefix softmax +
//   weighted reduction via warp shuffles.
// ~90 regs, 89 KB smem -> 2 blocks/SM = 16 warps (vs 8 before).
// ---------------------------------------------------------------------------
#define PTS   4
#define COLSB 128          // PTS*32 columns (j<30 real)
#define CSTR  132          // row stride (16B-aligned, bank-skewed)

#define SM_W1P   0         // 512
#define SM_B1    512       // 64
#define SM_B2    576       // 64
#define SM_WA    640       // 64
#define SM_AB    704       // 4
#define SM_ALOGP 708       // 256: [half][p][j]
#define SM_OUTS  964       // 256: [o][p]
#define SM_W2T   1232      // 4096: w2t[k][o] (16B aligned)
#define SM_H1    5328      // 64*CSTR = 8448
#define SM_H2    13776     // 8448
#define SM_TOT   22224     // floats (~88.9 KB)

__global__ __launch_bounds__(256, 2) void mlp_kernel(
    const float* __restrict__ x,
    const float* __restrict__ w1, const float* __restrict__ g1, const float* __restrict__ b1,
    const float* __restrict__ w2, const float* __restrict__ g2, const float* __restrict__ b2,
    const float* __restrict__ wa, const float* __restrict__ ba,
    const float* __restrict__ ga, const float* __restrict__ bga,
    float* __restrict__ out) {
    extern __shared__ float sm[];
    float* w1p   = sm + SM_W1P;
    float* b1s   = sm + SM_B1;
    float* b2s   = sm + SM_B2;
    float* was   = sm + SM_WA;
    float* abp   = sm + SM_AB;
    float* alogp = sm + SM_ALOGP;
    float* outs  = sm + SM_OUTS;
    float* w2t   = sm + SM_W2T;
    float* h1s   = sm + SM_H1;
    float* h2s   = sm + SM_H2;

    int tid = threadIdx.x;
    float sq = sqrtf(1.0f + 1e-5f);

    // ---- init weights ----
    {
        int t = tid >> 3, c = tid & 7;      // t<32
        if (c < 6) {
            w1p[(t * 8 + c) * 2 + 0] = w1[(2 * t) * 6 + c]     * (g1[2 * t]     / sq);
            w1p[(t * 8 + c) * 2 + 1] = w1[(2 * t + 1) * 6 + c] * (g1[2 * t + 1] / sq);
        } else {
            w1p[(t * 8 + c) * 2 + 0] = 0.f;
            w1p[(t * 8 + c) * 2 + 1] = 0.f;
        }
    }
    for (int i = tid; i < 64 * 64; i += 256) {   // w2t[k][o] = w2[o][k]*s2[o]
        int o = i & 63, k = i >> 6;
        w2t[i] = w2[o * 64 + k] * (g2[o] / sq);
    }
    if (tid < 64) {
        b1s[tid] = b1[tid];
        b2s[tid] = b2[tid];
        was[tid] = wa[tid] * (ga[0] / sq);
    }
    if (tid == 0) abp[0] = (ga[0] / sq) * ba[0] + bga[0];
    __syncthreads();

    int bb = blockIdx.x >> 10;               // 1024 blocks per batch element
    int nb = (blockIdx.x & 1023) * PTS;
    const float* xb = x + (size_t)bb * 3 * NN;

    // ---- Phase A: h1 for 128 columns (threads 0..127) ----
    if (tid < COLSB) {
        int p = tid >> 5, j = tid & 31;
        int n = nb + p;
        if (j < 30) {
            size_t P = (size_t)bb * NN + n;
            int m = g_knn[P * KK + j];
            float cx = xb[n], cy = xb[NN + n], cz = xb[2 * NN + n];
            float f0 = xb[m] - cx, f1 = xb[NN + m] - cy, f2 = xb[2 * NN + m] - cz;

            unsigned long long i0, i1, i2, i3, i4, i5;
            PACK2(i0, f0, f0); PACK2(i1, f1, f1); PACK2(i2, f2, f2);
            PACK2(i3, cx, cx); PACK2(i4, cy, cy); PACK2(i5, cz, cz);
            const unsigned long long* w1pu = (const unsigned long long*)w1p;
            const unsigned long long* b1u  = (const unsigned long long*)b1s;
            #pragma unroll
            for (int t = 0; t < 32; ++t) {
                const ulonglong2* wr = (const ulonglong2*)(w1pu + t * 8);
                unsigned long long acc = b1u[t];
                ulonglong2 wA = wr[0], wB = wr[1], wC = wr[2];
                FMA_F32X2(acc, wA.x, i0); FMA_F32X2(acc, wA.y, i1);
                FMA_F32X2(acc, wB.x, i2); FMA_F32X2(acc, wB.y, i3);
                FMA_F32X2(acc, wC.x, i4); FMA_F32X2(acc, wC.y, i5);
                float a, d;
                UNPACK2(a, d, acc);
                h1s[(2 * t) * CSTR + tid]     = fmaxf(a, 0.2f * a);
                h1s[(2 * t + 1) * CSTR + tid] = fmaxf(d, 0.2f * d);
            }
        } else {
            #pragma unroll
            for (int o = 0; o < 64; ++o) h1s[o * CSTR + tid] = 0.f;
        }
    }
    __syncthreads();

    // ---- Phase B: GEMM h2 = lrelu(w2 @ h1 + b2) ----
    {
        int w  = tid >> 5, lane = tid & 31;
        int r0 = (w >> 1) * 16 + (lane >> 3) * 4;   // 4 rows
        int c0 = (w & 1) * 64 + (lane & 7) * 8;     // 8 cols
        unsigned long long acc[4][4];
        #pragma unroll
        for (int i = 0; i < 4; ++i)
            #pragma unroll
            for (int q = 0; q < 4; ++q) acc[i][q] = 0ULL;

        #pragma unroll 4
        for (int k = 0; k < 64; ++k) {
            float4 a4 = *(const float4*)(w2t + k * 64 + r0);
            ulonglong2 B01 = *(const ulonglong2*)(h1s + k * CSTR + c0);
            ulonglong2 B23 = *(const ulonglong2*)(h1s + k * CSTR + c0 + 4);
            unsigned long long aa0, aa1, aa2, aa3;
            PACK2(aa0, a4.x, a4.x); PACK2(aa1, a4.y, a4.y);
            PACK2(aa2, a4.z, a4.z); PACK2(aa3, a4.w, a4.w);
            FMA_F32X2(acc[0][0], aa0, B01.x); FMA_F32X2(acc[0][1], aa0, B01.y);
            FMA_F32X2(acc[0][2], aa0, B23.x); FMA_F32X2(acc[0][3], aa0, B23.y);
            FMA_F32X2(acc[1][0], aa1, B01.x); FMA_F32X2(acc[1][1], aa1, B01.y);
            FMA_F32X2(acc[1][2], aa1, B23.x); FMA_F32X2(acc[1][3], aa1, B23.y);
            FMA_F32X2(acc[2][0], aa2, B01.x); FMA_F32X2(acc[2][1], aa2, B01.y);
            FMA_F32X2(acc[2][2], aa2, B23.x); FMA_F32X2(acc[2][3], aa2, B23.y);
            FMA_F32X2(acc[3][0], aa3, B01.x); FMA_F32X2(acc[3][1], aa3, B01.y);
            FMA_F32X2(acc[3][2], aa3, B23.x); FMA_F32X2(acc[3][3], aa3, B23.y);
        }

        #pragma unroll
        for (int i = 0; i < 4; ++i) {
            float bb2 = b2s[r0 + i];
            float v[8];
            #pragma unroll
            for (int q = 0; q < 4; ++q) {
                float lo, hi;
                UNPACK2(lo, hi, acc[i][q]);
                lo += bb2; hi += bb2;
                v[2 * q]     = fmaxf(lo, 0.2f * lo);
                v[2 * q + 1] = fmaxf(hi, 0.2f * hi);
            }
            *(float4*)(h2s + (r0 + i) * CSTR + c0)     = make_float4(v[0], v[1], v[2], v[3]);
            *(float4*)(h2s + (r0 + i) * CSTR + c0 + 4) = make_float4(v[4], v[5], v[6], v[7]);
        }
    }
    __syncthreads();

    // ---- Phase C: logits (split over 2 warps/point), softmax, reduce ----
    int w    = tid >> 5;
    int j    = tid & 31;
    int p    = w & 3;
    int half = w >> 2;              // o-range [32*half, 32*half+32)
    int cc   = p * 32 + j;

    {
        float part = 0.f;
        int obase = half * 32;
        #pragma unroll 8
        for (int oi = 0; oi < 32; ++oi)
            part += was[obase + oi] * h2s[(obase + oi) * CSTR + cc];
        alogp[half * 128 + cc] = part;
    }
    __syncthreads();

    float alog = abp[0] + alogp[cc] + alogp[128 + cc];
    alog = fmaxf(alog, 0.2f * alog);     // lrelu before softmax (reference)

    float wgt = 0.f;
    #pragma unroll
    for (int kk = 1; kk <= 3; ++kk) {
        int K = 10 * kk;
        float xv = (j < K) ? alog : -INFINITY;
        float mx = xv;
        #pragma unroll
        for (int d = 16; d; d >>= 1)
            mx = fmaxf(mx, __shfl_xor_sync(FULLMASK, mx, d));
        float e = (j < K) ? expf(alog - mx) : 0.f;
        float s = e;
        #pragma unroll
        for (int d = 16; d; d >>= 1)
            s += __shfl_xor_sync(FULLMASK, s, d);
        wgt += e / s;
    }
    wgt *= (1.0f / 3.0f);                // j>=30 -> wgt == 0 automatically

    {
        int obase = half * 32;
        #pragma unroll 4
        for (int oi = 0; oi < 32; ++oi) {
            int row = obase + oi;
            float v = wgt * h2s[row * CSTR + cc];
            #pragma unroll
            for (int d = 16; d; d >>= 1)
                v += __shfl_xor_sync(FULLMASK, v, d);
            if (j == 0) outs[row * 4 + p] = v;
        }
    }
    __syncthreads();

    {
        int c  = tid >> 2;               // 0..63
        int pp = tid & 3;
        out[((size_t)bb * 64 + c) * NN + nb + pp] = outs[c * 4 + pp];
    }
}

// ---------------------------------------------------------------------------

extern "C" void kernel_launch(void* const* d_in, const int* in_sizes, int n_in,
                              void* d_out, int out_size) {
    const float* x   = (const float*)d_in[0];
    const float* w1  = (const float*)d_in[1];
    const float* g1  = (const float*)d_in[2];
    const float* b1  = (const float*)d_in[3];
    const float* w2  = (const float*)d_in[4];
    const float* g2  = (const float*)d_in[5];
    const float* b2  = (const float*)d_in[6];
    const float* wa  = (const float*)d_in[7];
    const float* ba  = (const float*)d_in[8];
    const float* ga  = (const float*)d_in[9];
    const float* bga = (const float*)d_in[10];
    float* out = (float*)d_out;

    int knn_smem = NN * (int)sizeof(float4);      // 64 KB
    int mlp_smem = SM_TOT * (int)sizeof(float);   // ~89 KB

    cudaFuncSetAttribute(knn_kernel, cudaFuncAttributeMaxDynamicSharedMemorySize, knn_smem);
    cudaFuncSetAttribute(mlp_kernel, cudaFuncAttributeMaxDynamicSharedMemorySize, mlp_smem);

    knn_kernel<<<(NB * NN) / 8, 256, knn_smem>>>(x);
    mlp_kernel<<<(NB * NN) / PTS, 256, mlp_smem>>>(x, w1, g1, b1, w2, g2, b2,
                                                   wa, ba, ga, bga, out);
}